// round 1
// baseline (speedup 1.0000x reference)
#include <cuda_runtime.h>
#include <cuda_bf16.h>
#include <math.h>

// Problem constants
#define BB   64
#define NN   1025
#define DD   1024
#define CC   64
#define NB   (BB*NN)          // 65600 rows
#define LN_EPS 1e-5f

// Scratch (device globals: allocation-free)
__device__ float g_mu[NB];
__device__ float g_rs[NB];
__device__ float g_y[(size_t)NB*CC];   // after GEMM1 (pre-conv)
__device__ float g_z[(size_t)NB*CC];   // after conv block + gelu

__device__ __forceinline__ float gelu_exact(float v) {
    return v * normcdff(v);
}

// ---------------------------------------------------------------------------
// Kernel 1: LayerNorm statistics. One warp per row (row indexed by r=b*N+n).
// ---------------------------------------------------------------------------
__global__ __launch_bounds__(256) void k_stats(const float* __restrict__ x) {
    int r = blockIdx.x * 8 + (threadIdx.x >> 5);
    int lane = threadIdx.x & 31;
    if (r >= NB) return;
    int b = r / NN;
    int n = r - b * NN;
    const float4* xp = (const float4*)(x + (size_t)(n * BB + b) * DD);
    float s = 0.f, ss = 0.f;
#pragma unroll
    for (int i = 0; i < 8; i++) {
        float4 v = xp[lane + i * 32];
        s  += v.x + v.y + v.z + v.w;
        ss += v.x * v.x + v.y * v.y + v.z * v.z + v.w * v.w;
    }
#pragma unroll
    for (int o = 16; o; o >>= 1) {
        s  += __shfl_xor_sync(0xffffffffu, s, o);
        ss += __shfl_xor_sync(0xffffffffu, ss, o);
    }
    if (lane == 0) {
        float m   = s * (1.f / DD);
        float var = ss * (1.f / DD) - m * m;
        g_mu[r] = m;
        g_rs[r] = rsqrtf(var + LN_EPS);
    }
}

// ---------------------------------------------------------------------------
// Kernel 2: fused (LN-apply + scale) @ w1 + b1.  y[r][c], r=b*N+n.
// Tile: 64 rows x 64 cols, K-chunks of 32.
// ---------------------------------------------------------------------------
__global__ __launch_bounds__(256) void k_gemm1(
    const float* __restrict__ x,
    const float* __restrict__ ln_w, const float* __restrict__ ln_b,
    const float* __restrict__ gamma, const float* __restrict__ gammax,
    const float* __restrict__ w1, const float* __restrict__ b1)
{
    __shared__ float xs[32 * 66];   // [k][row], stride 66
    __shared__ float ws[32][64];
    __shared__ float sc1[DD], sc2[DD], sc3[DD];  // ln_w*gamma, gammax, ln_b*gamma
    __shared__ float smu[64], srs[64];
    __shared__ int   soff[64];

    int tid = threadIdx.x;
    int r0 = blockIdx.x * 64;

    for (int i = tid; i < DD; i += 256) {
        float g = gamma[i];
        sc1[i] = ln_w[i] * g;
        sc2[i] = gammax[i];
        sc3[i] = ln_b[i] * g;
    }
    if (tid < 64) {
        int r = r0 + tid;
        int b = r / NN;
        int n = r - b * NN;
        soff[tid] = (n * BB + b) * DD;
        smu[tid] = g_mu[r];
        srs[tid] = g_rs[r];
    }
    __syncthreads();

    float acc[4][4] = {};
    int cg = tid & 15;     // col group -> cols cg*4..cg*4+3
    int rg = tid >> 4;     // row group -> rows rg*4..rg*4+3

    for (int kc = 0; kc < DD; kc += 32) {
        // load + normalize x tile: 64 rows x 32 k = 512 float4
#pragma unroll
        for (int i = 0; i < 2; i++) {
            int s = tid + i * 256;
            int row = s >> 3;
            int kq = (s & 7) * 4;
            float4 v = *(const float4*)(x + soff[row] + kc + kq);
            float m = smu[row], rs = srs[row];
#pragma unroll
            for (int j = 0; j < 4; j++) {
                int k = kc + kq + j;
                float t = rs * sc1[k];
                float vv = (&v.x)[j];
                xs[(kq + j) * 66 + row] = vv * (t + sc2[k]) + (sc3[k] - m * t);
            }
        }
        // load w1 tile: 32 x 64
#pragma unroll
        for (int i = 0; i < 2; i++) {
            int s = tid + i * 256;
            int kk = s >> 4;
            int c = (s & 15) * 4;
            *(float4*)&ws[kk][c] = *(const float4*)(w1 + (size_t)(kc + kk) * CC + c);
        }
        __syncthreads();
#pragma unroll
        for (int k = 0; k < 32; k++) {
            float a[4], bb[4];
#pragma unroll
            for (int i = 0; i < 4; i++) a[i] = xs[k * 66 + rg * 4 + i];
            *(float4*)bb = *(const float4*)&ws[k][cg * 4];
#pragma unroll
            for (int i = 0; i < 4; i++)
#pragma unroll
                for (int j = 0; j < 4; j++) acc[i][j] += a[i] * bb[j];
        }
        __syncthreads();
    }

    float4 bias = *(const float4*)(b1 + cg * 4);
#pragma unroll
    for (int i = 0; i < 4; i++) {
        float4 o;
        o.x = acc[i][0] + bias.x;
        o.y = acc[i][1] + bias.y;
        o.z = acc[i][2] + bias.z;
        o.w = acc[i][3] + bias.w;
        *(float4*)(g_y + (size_t)(r0 + rg * 4 + i) * CC + cg * 4) = o;
    }
}

// ---------------------------------------------------------------------------
// Kernel 3: multi-scale depthwise conv (collapsed to one 7x7) + residual +
//           1x1 proj + residual + exact GELU.  Also handles cls token.
// Block = (batch, 4-row strip). 256 threads.
// smem: sIn[10 rows][38 cols][64 ch] + s2[4][32][64] + pws[64][64]
// ---------------------------------------------------------------------------
#define IN_ROWS 10
#define IN_COLS 38
#define IN_STRIDE (IN_COLS * 64)
#define SIN_SZ (IN_ROWS * IN_STRIDE)        // 24320 floats
#define S2_SZ  (4 * 32 * 64)                // 8192
#define PW_SZ  (64 * 64)                    // 4096
#define CONV_SMEM ((SIN_SZ + S2_SZ + PW_SZ) * sizeof(float))  // 146432 B

__global__ __launch_bounds__(256) void k_conv(
    const float* __restrict__ dw3_w, const float* __restrict__ dw3_b,
    const float* __restrict__ dw5_w, const float* __restrict__ dw5_b,
    const float* __restrict__ dw7_w, const float* __restrict__ dw7_b,
    const float* __restrict__ proj_w, const float* __restrict__ proj_b)
{
    extern __shared__ float sm[];
    float* sIn = sm;
    float* s2  = sm + SIN_SZ;
    float* pws = s2 + S2_SZ;

    int tid = threadIdx.x;
    int b = blockIdx.x >> 3;
    int strip = blockIdx.x & 7;
    int i0 = strip * 4;
    const float* yb = g_y + (size_t)b * NN * CC;

    // load input strip with halo (+zero SAME padding)
    for (int idx = tid; idx < SIN_SZ; idx += 256) {
        int rr  = idx / IN_STRIDE;
        int rem = idx - rr * IN_STRIDE;
        int col = rem >> 6;
        int c   = rem & 63;
        int gy = i0 - 3 + rr;
        int gx = col - 3;
        float v = 0.f;
        if (gy >= 0 && gy < 32 && gx >= 0 && gx < 32)
            v = yb[(size_t)(1 + gy * 32 + gx) * CC + c];
        sIn[idx] = v;
    }
    // proj weights transposed: pws[c][o] = proj_w[o][c]
    for (int idx = tid; idx < PW_SZ; idx += 256) {
        int c = idx >> 6, o = idx & 63;
        pws[idx] = proj_w[(size_t)o * CC + c];
    }

    // per-thread effective 7x7 weights for its channel
    int c = tid & 63;
    float wreg[49];
    float beff;
    {
        const float* w7 = dw7_w + c * 49;
        const float* w5 = dw5_w + c * 25;
        const float* w3 = dw3_w + c * 9;
#pragma unroll
        for (int dy = 0; dy < 7; dy++)
#pragma unroll
            for (int dx = 0; dx < 7; dx++) {
                float v = w7[dy * 7 + dx];
                if (dy >= 1 && dy <= 5 && dx >= 1 && dx <= 5) v += w5[(dy - 1) * 5 + (dx - 1)];
                if (dy >= 2 && dy <= 4 && dx >= 2 && dx <= 4) v += w3[(dy - 2) * 3 + (dx - 2)];
                wreg[dy * 7 + dx] = v * (1.f / 3.f);
            }
        beff = (dw3_b[c] + dw5_b[c] + dw7_b[c]) * (1.f / 3.f);
    }
    __syncthreads();

    // conv phase: thread = (row = tid>>6, channel c), sweeps 32 cols
    int row = tid >> 6;
#pragma unroll 2
    for (int j = 0; j < 32; j++) {
        float acc = beff;
#pragma unroll
        for (int dy = 0; dy < 7; dy++) {
            const float* rp = sIn + ((row + dy) * IN_COLS + j) * 64 + c;
#pragma unroll
            for (int dx = 0; dx < 7; dx++)
                acc += rp[dx * 64] * wreg[dy * 7 + dx];
        }
        float center = sIn[((row + 3) * IN_COLS + (j + 3)) * 64 + c];
        s2[(row * 32 + j) * 64 + c] = acc + center;
    }
    __syncthreads();

    // proj phase: out = s2 + (s2 @ projW^T + proj_b), then gelu, store z
    int og = tid & 15, pg = tid >> 4;
    int o0 = og * 4, px0 = pg * 8;
    float pacc[8][4] = {};
    for (int cc = 0; cc < 64; cc++) {
        float wv[4];
        *(float4*)wv = *(const float4*)&pws[cc * 64 + o0];
#pragma unroll
        for (int i = 0; i < 8; i++) {
            float sv = s2[(px0 + i) * 64 + cc];
#pragma unroll
            for (int j = 0; j < 4; j++) pacc[i][j] += sv * wv[j];
        }
    }
    float pb[4];
    *(float4*)pb = *(const float4*)(proj_b + o0);
#pragma unroll
    for (int i = 0; i < 8; i++) {
        int px = px0 + i;
        size_t zoff = ((size_t)b * NN + 1 + i0 * 32 + px) * CC + o0;
        float4 o;
        float v0 = s2[px * 64 + o0 + 0] + pacc[i][0] + pb[0];
        float v1 = s2[px * 64 + o0 + 1] + pacc[i][1] + pb[1];
        float v2 = s2[px * 64 + o0 + 2] + pacc[i][2] + pb[2];
        float v3 = s2[px * 64 + o0 + 3] + pacc[i][3] + pb[3];
        o.x = gelu_exact(v0); o.y = gelu_exact(v1);
        o.z = gelu_exact(v2); o.w = gelu_exact(v3);
        *(float4*)(g_z + zoff) = o;
    }

    // cls token (token 0): gelu(y) only
    if (strip == 0 && tid < 64) {
        float v = yb[tid];
        g_z[(size_t)b * NN * CC + tid] = gelu_exact(v);
    }
}

// ---------------------------------------------------------------------------
// Kernel 4: z @ w2 + b2 + identity(x) -> out (N,B,D layout).
// Tile: 64 rows x 128 cols, K=64 (full).
// ---------------------------------------------------------------------------
__global__ __launch_bounds__(256) void k_gemm2(
    const float* __restrict__ w2, const float* __restrict__ b2,
    const float* __restrict__ x, float* __restrict__ out)
{
    __shared__ float zs[64][65];
    __shared__ float w2s[64][128];
    int tid = threadIdx.x;
    int r0 = blockIdx.x * 64;
    int c0 = blockIdx.y * 128;

    // load z tile 64x64
#pragma unroll
    for (int i = 0; i < 4; i++) {
        int s = tid + i * 256;
        int row = s >> 4;
        int cc = (s & 15) * 4;
        float4 v = *(const float4*)(g_z + (size_t)(r0 + row) * CC + cc);
        zs[row][cc] = v.x; zs[row][cc + 1] = v.y;
        zs[row][cc + 2] = v.z; zs[row][cc + 3] = v.w;
    }
    // load w2 tile 64x128
#pragma unroll
    for (int i = 0; i < 8; i++) {
        int s = tid + i * 256;
        int k = s >> 5;
        int cc = (s & 31) * 4;
        *(float4*)&w2s[k][cc] = *(const float4*)(w2 + (size_t)k * DD + c0 + cc);
    }
    __syncthreads();

    int cg = tid & 15, rgp = tid >> 4;   // cols cg*8..+7, rows rgp*4..+3
    float acc[4][8] = {};
#pragma unroll
    for (int k = 0; k < 64; k++) {
        float a[4], bb[8];
#pragma unroll
        for (int i = 0; i < 4; i++) a[i] = zs[rgp * 4 + i][k];
        *(float4*)&bb[0] = *(const float4*)&w2s[k][cg * 8];
        *(float4*)&bb[4] = *(const float4*)&w2s[k][cg * 8 + 4];
#pragma unroll
        for (int i = 0; i < 4; i++)
#pragma unroll
            for (int j = 0; j < 8; j++) acc[i][j] += a[i] * bb[j];
    }

    float bb2[8];
    *(float4*)&bb2[0] = *(const float4*)(b2 + c0 + cg * 8);
    *(float4*)&bb2[4] = *(const float4*)(b2 + c0 + cg * 8 + 4);
#pragma unroll
    for (int i = 0; i < 4; i++) {
        int r = r0 + rgp * 4 + i;
        int b = r / NN;
        int n = r - b * NN;
        size_t off = (size_t)(n * BB + b) * DD + c0 + cg * 8;
        float4 x0 = *(const float4*)(x + off);
        float4 x1 = *(const float4*)(x + off + 4);
        float4 o0, o1;
        o0.x = x0.x + acc[i][0] + bb2[0];
        o0.y = x0.y + acc[i][1] + bb2[1];
        o0.z = x0.z + acc[i][2] + bb2[2];
        o0.w = x0.w + acc[i][3] + bb2[3];
        o1.x = x1.x + acc[i][4] + bb2[4];
        o1.y = x1.y + acc[i][5] + bb2[5];
        o1.z = x1.z + acc[i][6] + bb2[6];
        o1.w = x1.w + acc[i][7] + bb2[7];
        *(float4*)(out + off) = o0;
        *(float4*)(out + off + 4) = o1;
    }
}

// ---------------------------------------------------------------------------
extern "C" void kernel_launch(void* const* d_in, const int* in_sizes, int n_in,
                              void* d_out, int out_size) {
    const float* x      = (const float*)d_in[0];
    const float* ln_w   = (const float*)d_in[1];
    const float* ln_b   = (const float*)d_in[2];
    const float* gamma  = (const float*)d_in[3];
    const float* gammax = (const float*)d_in[4];
    const float* w1     = (const float*)d_in[5];
    const float* b1     = (const float*)d_in[6];
    const float* w2     = (const float*)d_in[7];
    const float* b2     = (const float*)d_in[8];
    const float* dw3_w  = (const float*)d_in[9];
    const float* dw3_b  = (const float*)d_in[10];
    const float* dw5_w  = (const float*)d_in[11];
    const float* dw5_b  = (const float*)d_in[12];
    const float* dw7_w  = (const float*)d_in[13];
    const float* dw7_b  = (const float*)d_in[14];
    const float* proj_w = (const float*)d_in[15];
    const float* proj_b = (const float*)d_in[16];
    float* out = (float*)d_out;

    cudaFuncSetAttribute(k_conv, cudaFuncAttributeMaxDynamicSharedMemorySize,
                         (int)CONV_SMEM);

    k_stats<<<NB / 8, 256>>>(x);
    k_gemm1<<<NB / 64, 256>>>(x, ln_w, ln_b, gamma, gammax, w1, b1);
    k_conv<<<BB * 8, 256, CONV_SMEM>>>(dw3_w, dw3_b, dw5_w, dw5_b,
                                       dw7_w, dw7_b, proj_w, proj_b);
    k_gemm2<<<dim3(NB / 64, DD / 128), 256>>>(w2, b2, x, out);
}

// round 3
// speedup vs baseline: 1.6376x; 1.6376x over previous
#include <cuda_runtime.h>
#include <cuda_bf16.h>
#include <cstdint>
#include <stdint.h>
#include <math.h>

// Problem constants
#define BB   64
#define NN   1025
#define DD   1024
#define CC   64
#define NB   (BB*NN)          // 65600 rows
#define LN_EPS 1e-5f

// Scratch (device globals: allocation-free)
__device__ float g_mu[NB];
__device__ float g_rs[NB];
__device__ float g_y[(size_t)NB*CC];            // after GEMM1 (fp32, conv input)
__device__ __nv_bfloat16 g_z[(size_t)NB*CC];    // after conv+gelu (bf16, GEMM2 A)

__device__ __forceinline__ float gelu_exact(float v) {
    return v * normcdff(v);
}

__device__ __forceinline__ unsigned smem_u32(const void* p) {
    return (unsigned)__cvta_generic_to_shared(p);
}

__device__ __forceinline__ void ldsm_x4(uint32_t (&r)[4], unsigned addr) {
    asm volatile("ldmatrix.sync.aligned.m8n8.x4.shared.b16 {%0,%1,%2,%3}, [%4];"
        : "=r"(r[0]), "=r"(r[1]), "=r"(r[2]), "=r"(r[3]) : "r"(addr));
}
__device__ __forceinline__ void ldsm_x2t(uint32_t (&r)[2], unsigned addr) {
    asm volatile("ldmatrix.sync.aligned.m8n8.x2.trans.shared.b16 {%0,%1}, [%2];"
        : "=r"(r[0]), "=r"(r[1]) : "r"(addr));
}
__device__ __forceinline__ void mma_bf16(float (&d)[4], const uint32_t (&a)[4],
                                         const uint32_t (&b)[2]) {
    asm volatile("mma.sync.aligned.m16n8k16.row.col.f32.bf16.bf16.f32 "
        "{%0,%1,%2,%3}, {%4,%5,%6,%7}, {%8,%9}, {%0,%1,%2,%3};"
        : "+f"(d[0]), "+f"(d[1]), "+f"(d[2]), "+f"(d[3])
        : "r"(a[0]), "r"(a[1]), "r"(a[2]), "r"(a[3]), "r"(b[0]), "r"(b[1]));
}

// ---------------------------------------------------------------------------
// Kernel 1: LayerNorm statistics. One warp per row (row r = b*N+n).
// ---------------------------------------------------------------------------
__global__ __launch_bounds__(256) void k_stats(const float* __restrict__ x) {
    int r = blockIdx.x * 8 + (threadIdx.x >> 5);
    int lane = threadIdx.x & 31;
    if (r >= NB) return;
    int b = r / NN;
    int n = r - b * NN;
    const float4* xp = (const float4*)(x + (size_t)(n * BB + b) * DD);
    float s = 0.f, ss = 0.f;
#pragma unroll
    for (int i = 0; i < 8; i++) {
        float4 v = xp[lane + i * 32];
        s  += v.x + v.y + v.z + v.w;
        ss += v.x * v.x + v.y * v.y + v.z * v.z + v.w * v.w;
    }
#pragma unroll
    for (int o = 16; o; o >>= 1) {
        s  += __shfl_xor_sync(0xffffffffu, s, o);
        ss += __shfl_xor_sync(0xffffffffu, ss, o);
    }
    if (lane == 0) {
        float m   = s * (1.f / DD);
        float var = ss * (1.f / DD) - m * m;
        g_mu[r] = m;
        g_rs[r] = rsqrtf(var + LN_EPS);
    }
}

// ---------------------------------------------------------------------------
// Kernel 2: fused (LN-apply + scale) @ w1 + b1 via bf16 tensor-core MMA.
// Tile: BM=128 rows x 64 cols, K-chunks of 64. 8 warps (4x2 over 128x64).
// ---------------------------------------------------------------------------
#define G1_BM 128
#define G1_BK 64
#define G1_SA 72     // bf16 stride, conflict-free + 16B-aligned rows
#define G1_SB 72

__global__ __launch_bounds__(256) void k_gemm1(
    const float* __restrict__ x,
    const float* __restrict__ ln_w, const float* __restrict__ ln_b,
    const float* __restrict__ gamma, const float* __restrict__ gammax,
    const float* __restrict__ w1, const float* __restrict__ b1)
{
    __shared__ __nv_bfloat16 sA[G1_BM * G1_SA];   // 18432 B
    __shared__ __nv_bfloat16 sB[G1_BK * G1_SB];   //  9216 B
    __shared__ float sc1[DD], sc2[DD], sc3[DD];   // 12288 B
    __shared__ float smu[G1_BM], srs[G1_BM];
    __shared__ int   soff[G1_BM];

    int tid = threadIdx.x;
    int lane = tid & 31, wid = tid >> 5;
    int warp_m = wid >> 1, warp_n = wid & 1;
    int r0 = blockIdx.x * G1_BM;

    for (int i = tid; i < DD; i += 256) {
        float g = gamma[i];
        sc1[i] = ln_w[i] * g;
        sc2[i] = gammax[i];
        sc3[i] = ln_b[i] * g;
    }
    if (tid < G1_BM) {
        int r = r0 + tid;
        int rr = (r < NB) ? r : 0;
        int b = rr / NN;
        int n = rr - b * NN;
        soff[tid] = (n * BB + b) * DD;
        smu[tid] = g_mu[rr];
        srs[tid] = g_rs[rr];
    }
    __syncthreads();

    float acc[2][4][4] = {};

    unsigned aAddr0 = smem_u32(&sA[(warp_m * 32 + (lane & 15)) * G1_SA + (lane >> 4) * 8]);
    unsigned bAddr0 = smem_u32(&sB[(lane & 15) * G1_SB + warp_n * 32]);

    for (int kc = 0; kc < DD; kc += G1_BK) {
        // A tile: 128 rows x 64 k, fp32 -> LN-affine -> bf16
#pragma unroll
        for (int i = 0; i < 8; i++) {
            int s = tid + i * 256;
            int row = s >> 4;
            int kq = (s & 15) * 4;
            float4 v = *(const float4*)(x + soff[row] + kc + kq);
            float m = smu[row], rs = srs[row];
            int k = kc + kq;
            float t0 = rs * sc1[k],     t1 = rs * sc1[k + 1];
            float t2 = rs * sc1[k + 2], t3 = rs * sc1[k + 3];
            float e0 = v.x * (t0 + sc2[k])     + (sc3[k]     - m * t0);
            float e1 = v.y * (t1 + sc2[k + 1]) + (sc3[k + 1] - m * t1);
            float e2 = v.z * (t2 + sc2[k + 2]) + (sc3[k + 2] - m * t2);
            float e3 = v.w * (t3 + sc2[k + 3]) + (sc3[k + 3] - m * t3);
            *(__nv_bfloat162*)&sA[row * G1_SA + kq]     = __floats2bfloat162_rn(e0, e1);
            *(__nv_bfloat162*)&sA[row * G1_SA + kq + 2] = __floats2bfloat162_rn(e2, e3);
        }
        // B tile: w1[kc..kc+63][0..63] fp32 -> bf16
#pragma unroll
        for (int i = 0; i < 4; i++) {
            int s = tid + i * 256;
            int kk = s >> 4;
            int c = (s & 15) * 4;
            float4 v = *(const float4*)(w1 + (size_t)(kc + kk) * CC + c);
            *(__nv_bfloat162*)&sB[kk * G1_SB + c]     = __floats2bfloat162_rn(v.x, v.y);
            *(__nv_bfloat162*)&sB[kk * G1_SB + c + 2] = __floats2bfloat162_rn(v.z, v.w);
        }
        __syncthreads();
#pragma unroll
        for (int ks = 0; ks < 4; ks++) {
            uint32_t a[2][4], b[4][2];
            ldsm_x4(a[0], aAddr0 + ks * 32);
            ldsm_x4(a[1], aAddr0 + 16 * G1_SA * 2 + ks * 32);
#pragma unroll
            for (int ni = 0; ni < 4; ni++)
                ldsm_x2t(b[ni], bAddr0 + ks * 16 * G1_SB * 2 + ni * 16);
#pragma unroll
            for (int mi = 0; mi < 2; mi++)
#pragma unroll
                for (int ni = 0; ni < 4; ni++)
                    mma_bf16(acc[mi][ni], a[mi], b[ni]);
        }
        __syncthreads();
    }

    // epilogue: + b1, store y (fp32)
    int row_in = lane >> 2;
    int colq = (lane & 3) * 2;
#pragma unroll
    for (int mi = 0; mi < 2; mi++) {
#pragma unroll
        for (int ni = 0; ni < 4; ni++) {
            int col = warp_n * 32 + ni * 8 + colq;
            float2 bias = *(const float2*)(b1 + col);
            int r = r0 + warp_m * 32 + mi * 16 + row_in;
            if (r < NB) {
                float2 o = {acc[mi][ni][0] + bias.x, acc[mi][ni][1] + bias.y};
                *(float2*)(g_y + (size_t)r * CC + col) = o;
            }
            int r2 = r + 8;
            if (r2 < NB) {
                float2 o = {acc[mi][ni][2] + bias.x, acc[mi][ni][3] + bias.y};
                *(float2*)(g_y + (size_t)r2 * CC + col) = o;
            }
        }
    }
}

// ---------------------------------------------------------------------------
// Kernel 3: multi-scale depthwise conv (collapsed 7x7) + residual + 1x1 proj
//           + residual + exact GELU -> z (bf16). Handles cls token.
// ---------------------------------------------------------------------------
#define IN_ROWS 10
#define IN_COLS 38
#define IN_STRIDE (IN_COLS * 64)
#define SIN_SZ (IN_ROWS * IN_STRIDE)
#define S2_SZ  (4 * 32 * 64)
#define PW_SZ  (64 * 64)
#define CONV_SMEM ((SIN_SZ + S2_SZ + PW_SZ) * sizeof(float))

__global__ __launch_bounds__(256) void k_conv(
    const float* __restrict__ dw3_w, const float* __restrict__ dw3_b,
    const float* __restrict__ dw5_w, const float* __restrict__ dw5_b,
    const float* __restrict__ dw7_w, const float* __restrict__ dw7_b,
    const float* __restrict__ proj_w, const float* __restrict__ proj_b)
{
    extern __shared__ float sm[];
    float* sIn = sm;
    float* s2  = sm + SIN_SZ;
    float* pws = s2 + S2_SZ;

    int tid = threadIdx.x;
    int b = blockIdx.x >> 3;
    int strip = blockIdx.x & 7;
    int i0 = strip * 4;
    const float* yb = g_y + (size_t)b * NN * CC;

    for (int idx = tid; idx < SIN_SZ; idx += 256) {
        int rr  = idx / IN_STRIDE;
        int rem = idx - rr * IN_STRIDE;
        int col = rem >> 6;
        int c   = rem & 63;
        int gy = i0 - 3 + rr;
        int gx = col - 3;
        float v = 0.f;
        if (gy >= 0 && gy < 32 && gx >= 0 && gx < 32)
            v = yb[(size_t)(1 + gy * 32 + gx) * CC + c];
        sIn[idx] = v;
    }
    for (int idx = tid; idx < PW_SZ; idx += 256) {
        int c = idx >> 6, o = idx & 63;
        pws[idx] = proj_w[(size_t)o * CC + c];
    }

    int c = tid & 63;
    float wreg[49];
    float beff;
    {
        const float* w7 = dw7_w + c * 49;
        const float* w5 = dw5_w + c * 25;
        const float* w3 = dw3_w + c * 9;
#pragma unroll
        for (int dy = 0; dy < 7; dy++)
#pragma unroll
            for (int dx = 0; dx < 7; dx++) {
                float v = w7[dy * 7 + dx];
                if (dy >= 1 && dy <= 5 && dx >= 1 && dx <= 5) v += w5[(dy - 1) * 5 + (dx - 1)];
                if (dy >= 2 && dy <= 4 && dx >= 2 && dx <= 4) v += w3[(dy - 2) * 3 + (dx - 2)];
                wreg[dy * 7 + dx] = v * (1.f / 3.f);
            }
        beff = (dw3_b[c] + dw5_b[c] + dw7_b[c]) * (1.f / 3.f);
    }
    __syncthreads();

    int row = tid >> 6;
#pragma unroll 2
    for (int j = 0; j < 32; j++) {
        float acc = beff;
#pragma unroll
        for (int dy = 0; dy < 7; dy++) {
            const float* rp = sIn + ((row + dy) * IN_COLS + j) * 64 + c;
#pragma unroll
            for (int dx = 0; dx < 7; dx++)
                acc += rp[dx * 64] * wreg[dy * 7 + dx];
        }
        float center = sIn[((row + 3) * IN_COLS + (j + 3)) * 64 + c];
        s2[(row * 32 + j) * 64 + c] = acc + center;
    }
    __syncthreads();

    int og = tid & 15, pg = tid >> 4;
    int o0 = og * 4, px0 = pg * 8;
    float pacc[8][4] = {};
    for (int cc = 0; cc < 64; cc++) {
        float wv[4];
        *(float4*)wv = *(const float4*)&pws[cc * 64 + o0];
#pragma unroll
        for (int i = 0; i < 8; i++) {
            float sv = s2[(px0 + i) * 64 + cc];
#pragma unroll
            for (int j = 0; j < 4; j++) pacc[i][j] += sv * wv[j];
        }
    }
    float pb[4];
    *(float4*)pb = *(const float4*)(proj_b + o0);
#pragma unroll
    for (int i = 0; i < 8; i++) {
        int px = px0 + i;
        size_t zoff = ((size_t)b * NN + 1 + i0 * 32 + px) * CC + o0;
        float v0 = gelu_exact(s2[px * 64 + o0 + 0] + pacc[i][0] + pb[0]);
        float v1 = gelu_exact(s2[px * 64 + o0 + 1] + pacc[i][1] + pb[1]);
        float v2 = gelu_exact(s2[px * 64 + o0 + 2] + pacc[i][2] + pb[2]);
        float v3 = gelu_exact(s2[px * 64 + o0 + 3] + pacc[i][3] + pb[3]);
        *(__nv_bfloat162*)(g_z + zoff)     = __floats2bfloat162_rn(v0, v1);
        *(__nv_bfloat162*)(g_z + zoff + 2) = __floats2bfloat162_rn(v2, v3);
    }

    if (strip == 0 && tid < 64) {
        float v = yb[tid];
        g_z[(size_t)b * NN * CC + tid] = __float2bfloat16(gelu_exact(v));
    }
}

// ---------------------------------------------------------------------------
// Kernel 4: z(bf16) @ w2 + b2 + identity(x) -> out via tensor-core MMA.
// Tile: 128 x 128, K=64 full. 8 warps (4x2), warp tile 32x64.
// ---------------------------------------------------------------------------
#define G2_BM 128
#define G2_BN 128
#define G2_SA 72
#define G2_SB 136

__global__ __launch_bounds__(256) void k_gemm2(
    const float* __restrict__ w2, const float* __restrict__ b2,
    const float* __restrict__ x, float* __restrict__ out)
{
    __shared__ __nv_bfloat16 sA[G2_BM * G2_SA];  // 18432 B
    __shared__ __nv_bfloat16 sB[64 * G2_SB];     // 17408 B

    int tid = threadIdx.x, lane = tid & 31, wid = tid >> 5;
    int warp_m = wid >> 1, warp_n = wid & 1;
    int r0 = blockIdx.x * G2_BM;
    int c0 = blockIdx.y * G2_BN;

    // A tile: z bf16, 128 x 64
#pragma unroll
    for (int i = 0; i < 4; i++) {
        int s = tid + i * 256;
        int row = s >> 3;
        int cq = (s & 7) * 8;
        int r = r0 + row;
        uint4 v = make_uint4(0, 0, 0, 0);
        if (r < NB) v = *(const uint4*)(g_z + (size_t)r * CC + cq);
        *(uint4*)&sA[row * G2_SA + cq] = v;
    }
    // B tile: w2[0..63][c0..c0+127] fp32 -> bf16
#pragma unroll
    for (int i = 0; i < 8; i++) {
        int s = tid + i * 256;
        int k = s >> 5;
        int cc = (s & 31) * 4;
        float4 v = *(const float4*)(w2 + (size_t)k * DD + c0 + cc);
        *(__nv_bfloat162*)&sB[k * G2_SB + cc]     = __floats2bfloat162_rn(v.x, v.y);
        *(__nv_bfloat162*)&sB[k * G2_SB + cc + 2] = __floats2bfloat162_rn(v.z, v.w);
    }
    __syncthreads();

    float acc[2][8][4] = {};
    unsigned aAddr0 = smem_u32(&sA[(warp_m * 32 + (lane & 15)) * G2_SA + (lane >> 4) * 8]);
    unsigned bAddr0 = smem_u32(&sB[(lane & 15) * G2_SB + warp_n * 64]);

#pragma unroll
    for (int ks = 0; ks < 4; ks++) {
        uint32_t a[2][4];
        ldsm_x4(a[0], aAddr0 + ks * 32);
        ldsm_x4(a[1], aAddr0 + 16 * G2_SA * 2 + ks * 32);
#pragma unroll
        for (int ni = 0; ni < 8; ni++) {
            uint32_t b[2];
            ldsm_x2t(b, bAddr0 + ks * 16 * G2_SB * 2 + ni * 16);
            mma_bf16(acc[0][ni], a[0], b);
            mma_bf16(acc[1][ni], a[1], b);
        }
    }

    // epilogue: out = x + acc + b2
    int row_in = lane >> 2, colq = (lane & 3) * 2;
#pragma unroll
    for (int mi = 0; mi < 2; mi++) {
#pragma unroll
        for (int h = 0; h < 2; h++) {
            int r = r0 + warp_m * 32 + mi * 16 + row_in + h * 8;
            if (r >= NB) continue;
            int b = r / NN, n = r - b * NN;
            size_t base = (size_t)(n * BB + b) * DD + c0 + warp_n * 64 + colq;
#pragma unroll
            for (int ni = 0; ni < 8; ni++) {
                size_t off = base + ni * 8;
                float2 bias = *(const float2*)(b2 + c0 + warp_n * 64 + ni * 8 + colq);
                float2 xv = *(const float2*)(x + off);
                float2 o = {xv.x + acc[mi][ni][2 * h]     + bias.x,
                            xv.y + acc[mi][ni][2 * h + 1] + bias.y};
                *(float2*)(out + off) = o;
            }
        }
    }
}

// ---------------------------------------------------------------------------
extern "C" void kernel_launch(void* const* d_in, const int* in_sizes, int n_in,
                              void* d_out, int out_size) {
    const float* x      = (const float*)d_in[0];
    const float* ln_w   = (const float*)d_in[1];
    const float* ln_b   = (const float*)d_in[2];
    const float* gamma  = (const float*)d_in[3];
    const float* gammax = (const float*)d_in[4];
    const float* w1     = (const float*)d_in[5];
    const float* b1     = (const float*)d_in[6];
    const float* w2     = (const float*)d_in[7];
    const float* b2     = (const float*)d_in[8];
    const float* dw3_w  = (const float*)d_in[9];
    const float* dw3_b  = (const float*)d_in[10];
    const float* dw5_w  = (const float*)d_in[11];
    const float* dw5_b  = (const float*)d_in[12];
    const float* dw7_w  = (const float*)d_in[13];
    const float* dw7_b  = (const float*)d_in[14];
    const float* proj_w = (const float*)d_in[15];
    const float* proj_b = (const float*)d_in[16];
    float* out = (float*)d_out;

    cudaFuncSetAttribute(k_conv, cudaFuncAttributeMaxDynamicSharedMemorySize,
                         (int)CONV_SMEM);

    k_stats<<<NB / 8, 256>>>(x);
    k_gemm1<<<(NB + G1_BM - 1) / G1_BM, 256>>>(x, ln_w, ln_b, gamma, gammax, w1, b1);
    k_conv<<<BB * 8, 256, CONV_SMEM>>>(dw3_w, dw3_b, dw5_w, dw5_b,
                                       dw7_w, dw7_b, proj_w, proj_b);
    k_gemm2<<<dim3((NB + G2_BM - 1) / G2_BM, DD / G2_BN), 256>>>(w2, b2, x, out);
}

// round 5
// speedup vs baseline: 1.7461x; 1.0663x over previous
#include <cuda_runtime.h>
#include <cuda_bf16.h>
#include <cstdint>
#include <stdint.h>
#include <math.h>

// Problem constants
#define BB   64
#define NN   1025
#define DD   1024
#define CC   64
#define NB   (BB*NN)          // 65600 rows
#define LN_EPS 1e-5f

// Scratch (device globals: allocation-free)
__device__ float g_y[(size_t)NB*CC];            // after GEMM1 (fp32, conv input)
__device__ __nv_bfloat16 g_z[(size_t)NB*CC];    // after conv+gelu (bf16, GEMM2 A)
__device__ __nv_bfloat16 g_w1a[(size_t)DD*CC];  // (ln_w*gamma) ⊙ w1, bf16
__device__ __nv_bfloat16 g_w1b[(size_t)DD*CC];  // gammax ⊙ w1, bf16
__device__ float g_S1p[16][CC];                 // partial col-sums of sc1*w1
__device__ float g_C3p[16][CC];                 // partial col-sums of sc3*w1

__device__ __forceinline__ float gelu_exact(float v) {
    return v * normcdff(v);
}
__device__ __forceinline__ unsigned smem_u32(const void* p) {
    return (unsigned)__cvta_generic_to_shared(p);
}
__device__ __forceinline__ void ldsm_x4(uint32_t (&r)[4], unsigned addr) {
    asm volatile("ldmatrix.sync.aligned.m8n8.x4.shared.b16 {%0,%1,%2,%3}, [%4];"
        : "=r"(r[0]), "=r"(r[1]), "=r"(r[2]), "=r"(r[3]) : "r"(addr));
}
__device__ __forceinline__ void ldsm_x2t(uint32_t (&r)[2], unsigned addr) {
    asm volatile("ldmatrix.sync.aligned.m8n8.x2.trans.shared.b16 {%0,%1}, [%2];"
        : "=r"(r[0]), "=r"(r[1]) : "r"(addr));
}
__device__ __forceinline__ void mma_bf16(float (&d)[4], const uint32_t (&a)[4],
                                         const uint32_t (&b)[2]) {
    asm volatile("mma.sync.aligned.m16n8k16.row.col.f32.bf16.bf16.f32 "
        "{%0,%1,%2,%3}, {%4,%5,%6,%7}, {%8,%9}, {%0,%1,%2,%3};"
        : "+f"(d[0]), "+f"(d[1]), "+f"(d[2]), "+f"(d[3])
        : "r"(a[0]), "r"(a[1]), "r"(a[2]), "r"(a[3]), "r"(b[0]), "r"(b[1]));
}

// ---------------------------------------------------------------------------
// Kernel 0: prep. Bake LN scales into w1 (bf16) + partial column sums.
// ---------------------------------------------------------------------------
__global__ __launch_bounds__(256) void k_prep(
    const float* __restrict__ ln_w, const float* __restrict__ ln_b,
    const float* __restrict__ gamma, const float* __restrict__ gammax,
    const float* __restrict__ w1)
{
    __shared__ float redS[4][CC];
    __shared__ float redC[4][CC];
    int tid = threadIdx.x;
    int k0 = blockIdx.x * 64;
    int c = tid & 63;
    int kg = tid >> 6;
    float s1p = 0.f, c3p = 0.f;
#pragma unroll
    for (int i = 0; i < 16; i++) {
        int kk = kg + 4 * i;
        int k = k0 + kk;
        float w = w1[(size_t)k * CC + c];
        float g = gamma[k];
        float sc1 = ln_w[k] * g;
        float sc3 = ln_b[k] * g;
        float sc2 = gammax[k];
        g_w1a[(size_t)k * CC + c] = __float2bfloat16(sc1 * w);
        g_w1b[(size_t)k * CC + c] = __float2bfloat16(sc2 * w);
        s1p += sc1 * w;
        c3p += sc3 * w;
    }
    redS[kg][c] = s1p;
    redC[kg][c] = c3p;
    __syncthreads();
    if (tid < 64) {
        g_S1p[blockIdx.x][tid] = redS[0][tid] + redS[1][tid] + redS[2][tid] + redS[3][tid];
        g_C3p[blockIdx.x][tid] = redC[0][tid] + redC[1][tid] + redC[2][tid] + redC[3][tid];
    }
}

// ---------------------------------------------------------------------------
// Kernel 1: fused LN-stats + decomposed GEMM1.
// y = rs*acc1 + acc2 + C3 - mu*rs*S1 + b1, acc1 = x@(sc1 w1), acc2 = x@(sc2 w1).
// Tile 128 x 64, K-chunks of 64. 8 warps (4x2), warp tile 32x32.
// ---------------------------------------------------------------------------
#define F1_SA 72
#define F1_SB 72

__global__ __launch_bounds__(256) void k_fused1(
    const float* __restrict__ x, const float* __restrict__ b1)
{
    __shared__ __nv_bfloat16 sA[128 * F1_SA];    // 18432 B
    __shared__ __nv_bfloat16 sB1[64 * F1_SB];    //  9216 B
    __shared__ __nv_bfloat16 sB2[64 * F1_SB];    //  9216 B
    __shared__ float sS1[CC], sC3[CC];
    __shared__ float smu[128], srs[128];
    __shared__ int   soff[128];

    int tid = threadIdx.x;
    int lane = tid & 31, wid = tid >> 5;
    int warp_m = wid >> 1, warp_n = wid & 1;
    int r0 = blockIdx.x * 128;

    if (tid < 64) {
        float s1 = 0.f, c3 = 0.f;
#pragma unroll
        for (int p = 0; p < 16; p++) { s1 += g_S1p[p][tid]; c3 += g_C3p[p][tid]; }
        sS1[tid] = s1;
        sC3[tid] = c3;
    }
    if (tid < 128) {
        int r = r0 + tid;
        int rr = (r < NB) ? r : 0;
        int b = rr / NN;
        int n = rr - b * NN;
        soff[tid] = (n * BB + b) * DD;
    }
    __syncthreads();

    float acc1[2][4][4] = {};
    float acc2[2][4][4] = {};
    float sumx[8] = {}, sumxx[8] = {};

    unsigned aAddr0 = smem_u32(&sA[(warp_m * 32 + (lane & 15)) * F1_SA + (lane >> 4) * 8]);
    unsigned b1Addr0 = smem_u32(&sB1[(lane & 15) * F1_SB + warp_n * 32]);
    unsigned b2Addr0 = smem_u32(&sB2[(lane & 15) * F1_SB + warp_n * 32]);

    int rowA = tid >> 4;
    int kqA = (tid & 15) * 4;

    for (int kc = 0; kc < DD; kc += 64) {
        // A tile: raw x -> bf16; accumulate row stats on the fly
#pragma unroll
        for (int i = 0; i < 8; i++) {
            int row = rowA + 16 * i;
            float4 v = *(const float4*)(x + soff[row] + kc + kqA);
            sumx[i]  += v.x + v.y + v.z + v.w;
            sumxx[i] += v.x * v.x + v.y * v.y + v.z * v.z + v.w * v.w;
            *(__nv_bfloat162*)&sA[row * F1_SA + kqA]     = __floats2bfloat162_rn(v.x, v.y);
            *(__nv_bfloat162*)&sA[row * F1_SA + kqA + 2] = __floats2bfloat162_rn(v.z, v.w);
        }
        // B tiles: pre-baked bf16, straight copies (8 bf16 per uint4)
#pragma unroll
        for (int i = 0; i < 2; i++) {
            int s = tid + i * 256;
            int kk = s >> 3;
            int q = (s & 7) * 8;
            *(uint4*)&sB1[kk * F1_SB + q] = *(const uint4*)(g_w1a + (size_t)(kc + kk) * CC + q);
            *(uint4*)&sB2[kk * F1_SB + q] = *(const uint4*)(g_w1b + (size_t)(kc + kk) * CC + q);
        }
        __syncthreads();
#pragma unroll
        for (int ks = 0; ks < 4; ks++) {
            uint32_t a[2][4];
            ldsm_x4(a[0], aAddr0 + ks * 32);
            ldsm_x4(a[1], aAddr0 + 16 * F1_SA * 2 + ks * 32);
#pragma unroll
            for (int ni = 0; ni < 4; ni++) {
                uint32_t bb1[2], bb2[2];
                ldsm_x2t(bb1, b1Addr0 + ks * 16 * F1_SB * 2 + ni * 16);
                ldsm_x2t(bb2, b2Addr0 + ks * 16 * F1_SB * 2 + ni * 16);
#pragma unroll
                for (int mi = 0; mi < 2; mi++) {
                    mma_bf16(acc1[mi][ni], a[mi], bb1);
                    mma_bf16(acc2[mi][ni], a[mi], bb2);
                }
            }
        }
        __syncthreads();
    }

    // finalize row stats: reduce over the 16 lanes sharing each row
#pragma unroll
    for (int i = 0; i < 8; i++) {
#pragma unroll
        for (int o = 8; o; o >>= 1) {
            sumx[i]  += __shfl_xor_sync(0xffffffffu, sumx[i], o);
            sumxx[i] += __shfl_xor_sync(0xffffffffu, sumxx[i], o);
        }
    }
    if ((tid & 15) == 0) {
#pragma unroll
        for (int i = 0; i < 8; i++) {
            int row = rowA + 16 * i;
            float m = sumx[i] * (1.f / DD);
            float var = sumxx[i] * (1.f / DD) - m * m;
            smu[row] = m;
            srs[row] = rsqrtf(var + LN_EPS);
        }
    }
    __syncthreads();

    // epilogue
    int row_in = lane >> 2;
    int colq = (lane & 3) * 2;
#pragma unroll
    for (int mi = 0; mi < 2; mi++) {
#pragma unroll
        for (int h = 0; h < 2; h++) {
            int rl = warp_m * 32 + mi * 16 + row_in + h * 8;
            int r = r0 + rl;
            if (r >= NB) continue;
            float mu = smu[rl], rs = srs[rl];
            float mrs = mu * rs;
#pragma unroll
            for (int ni = 0; ni < 4; ni++) {
                int col = warp_n * 32 + ni * 8 + colq;
                float2 bias = *(const float2*)(b1 + col);
                float v0 = rs * acc1[mi][ni][2 * h]     + acc2[mi][ni][2 * h]
                         + sC3[col]     - mrs * sS1[col]     + bias.x;
                float v1 = rs * acc1[mi][ni][2 * h + 1] + acc2[mi][ni][2 * h + 1]
                         + sC3[col + 1] - mrs * sS1[col + 1] + bias.y;
                *(float2*)(g_y + (size_t)r * CC + col) = make_float2(v0, v1);
            }
        }
    }
}

// ---------------------------------------------------------------------------
// Kernel 3: multi-scale depthwise conv (collapsed 7x7) + residual + 1x1 proj
//           + residual + exact GELU -> z (bf16). Handles cls token.
// ---------------------------------------------------------------------------
#define IN_ROWS 10
#define IN_COLS 38
#define IN_STRIDE (IN_COLS * 64)
#define SIN_SZ (IN_ROWS * IN_STRIDE)
#define S2_SZ  (4 * 32 * 64)
#define PW_SZ  (64 * 64)
#define CONV_SMEM ((SIN_SZ + S2_SZ + PW_SZ) * sizeof(float))

__global__ __launch_bounds__(256) void k_conv(
    const float* __restrict__ dw3_w, const float* __restrict__ dw3_b,
    const float* __restrict__ dw5_w, const float* __restrict__ dw5_b,
    const float* __restrict__ dw7_w, const float* __restrict__ dw7_b,
    const float* __restrict__ proj_w, const float* __restrict__ proj_b)
{
    extern __shared__ float sm[];
    float* sIn = sm;
    float* s2  = sm + SIN_SZ;
    float* pws = s2 + S2_SZ;

    int tid = threadIdx.x;
    int b = blockIdx.x >> 3;
    int strip = blockIdx.x & 7;
    int i0 = strip * 4;
    const float* yb = g_y + (size_t)b * NN * CC;

    for (int idx = tid; idx < SIN_SZ; idx += 256) {
        int rr  = idx / IN_STRIDE;
        int rem = idx - rr * IN_STRIDE;
        int col = rem >> 6;
        int c   = rem & 63;
        int gy = i0 - 3 + rr;
        int gx = col - 3;
        float v = 0.f;
        if (gy >= 0 && gy < 32 && gx >= 0 && gx < 32)
            v = yb[(size_t)(1 + gy * 32 + gx) * CC + c];
        sIn[idx] = v;
    }
    for (int idx = tid; idx < PW_SZ; idx += 256) {
        int c = idx >> 6, o = idx & 63;
        pws[idx] = proj_w[(size_t)o * CC + c];
    }

    int c = tid & 63;
    float wreg[49];
    float beff;
    {
        const float* w7 = dw7_w + c * 49;
        const float* w5 = dw5_w + c * 25;
        const float* w3 = dw3_w + c * 9;
#pragma unroll
        for (int dy = 0; dy < 7; dy++)
#pragma unroll
            for (int dx = 0; dx < 7; dx++) {
                float v = w7[dy * 7 + dx];
                if (dy >= 1 && dy <= 5 && dx >= 1 && dx <= 5) v += w5[(dy - 1) * 5 + (dx - 1)];
                if (dy >= 2 && dy <= 4 && dx >= 2 && dx <= 4) v += w3[(dy - 2) * 3 + (dx - 2)];
                wreg[dy * 7 + dx] = v * (1.f / 3.f);
            }
        beff = (dw3_b[c] + dw5_b[c] + dw7_b[c]) * (1.f / 3.f);
    }
    __syncthreads();

    int row = tid >> 6;
#pragma unroll 2
    for (int j = 0; j < 32; j++) {
        float acc = beff;
#pragma unroll
        for (int dy = 0; dy < 7; dy++) {
            const float* rp = sIn + ((row + dy) * IN_COLS + j) * 64 + c;
#pragma unroll
            for (int dx = 0; dx < 7; dx++)
                acc += rp[dx * 64] * wreg[dy * 7 + dx];
        }
        float center = sIn[((row + 3) * IN_COLS + (j + 3)) * 64 + c];
        s2[(row * 32 + j) * 64 + c] = acc + center;
    }
    __syncthreads();

    int og = tid & 15, pg = tid >> 4;
    int o0 = og * 4, px0 = pg * 8;
    float pacc[8][4] = {};
    for (int cc = 0; cc < 64; cc++) {
        float wv[4];
        *(float4*)wv = *(const float4*)&pws[cc * 64 + o0];
#pragma unroll
        for (int i = 0; i < 8; i++) {
            float sv = s2[(px0 + i) * 64 + cc];
#pragma unroll
            for (int j = 0; j < 4; j++) pacc[i][j] += sv * wv[j];
        }
    }
    float pb[4];
    *(float4*)pb = *(const float4*)(proj_b + o0);
#pragma unroll
    for (int i = 0; i < 8; i++) {
        int px = px0 + i;
        size_t zoff = ((size_t)b * NN + 1 + i0 * 32 + px) * CC + o0;
        float v0 = gelu_exact(s2[px * 64 + o0 + 0] + pacc[i][0] + pb[0]);
        float v1 = gelu_exact(s2[px * 64 + o0 + 1] + pacc[i][1] + pb[1]);
        float v2 = gelu_exact(s2[px * 64 + o0 + 2] + pacc[i][2] + pb[2]);
        float v3 = gelu_exact(s2[px * 64 + o0 + 3] + pacc[i][3] + pb[3]);
        *(__nv_bfloat162*)(g_z + zoff)     = __floats2bfloat162_rn(v0, v1);
        *(__nv_bfloat162*)(g_z + zoff + 2) = __floats2bfloat162_rn(v2, v3);
    }

    if (strip == 0 && tid < 64) {
        float v = yb[tid];
        g_z[(size_t)b * NN * CC + tid] = __float2bfloat16(gelu_exact(v));
    }
}

// ---------------------------------------------------------------------------
// Kernel 4: z(bf16) @ w2 + b2 + identity(x) -> out. Tile 128x64, K=64.
// 8 warps (4x2), warp tile 32x32 -> fewer regs, higher occupancy.
// ---------------------------------------------------------------------------
#define G2_SA 72
#define G2_SB 72

__global__ __launch_bounds__(256) void k_gemm2(
    const float* __restrict__ w2, const float* __restrict__ b2,
    const float* __restrict__ x, float* __restrict__ out)
{
    __shared__ __nv_bfloat16 sA[128 * G2_SA];  // 18432 B
    __shared__ __nv_bfloat16 sB[64 * G2_SB];   //  9216 B

    int tid = threadIdx.x, lane = tid & 31, wid = tid >> 5;
    int warp_m = wid >> 1, warp_n = wid & 1;
    int r0 = blockIdx.x * 128;
    int c0 = blockIdx.y * 64;

    // A tile: z bf16, 128 x 64  (128*64/8 = 1024 uint4 -> 4 iterations of 256)
#pragma unroll
    for (int i = 0; i < 4; i++) {
        int s = tid + i * 256;
        int row = s >> 3;
        int cq = (s & 7) * 8;
        int r = r0 + row;
        uint4 v = make_uint4(0, 0, 0, 0);
        if (r < NB) v = *(const uint4*)(g_z + (size_t)r * CC + cq);
        *(uint4*)&sA[row * G2_SA + cq] = v;
    }
    // B tile: w2[0..63][c0..c0+63] fp32 -> bf16
#pragma unroll
    for (int i = 0; i < 4; i++) {
        int s = tid + i * 256;
        int k = s >> 4;
        int cc = (s & 15) * 4;
        float4 v = *(const float4*)(w2 + (size_t)k * DD + c0 + cc);
        *(__nv_bfloat162*)&sB[k * G2_SB + cc]     = __floats2bfloat162_rn(v.x, v.y);
        *(__nv_bfloat162*)&sB[k * G2_SB + cc + 2] = __floats2bfloat162_rn(v.z, v.w);
    }
    __syncthreads();

    float acc[2][4][4] = {};
    unsigned aAddr0 = smem_u32(&sA[(warp_m * 32 + (lane & 15)) * G2_SA + (lane >> 4) * 8]);
    unsigned bAddr0 = smem_u32(&sB[(lane & 15) * G2_SB + warp_n * 32]);

#pragma unroll
    for (int ks = 0; ks < 4; ks++) {
        uint32_t a[2][4];
        ldsm_x4(a[0], aAddr0 + ks * 32);
        ldsm_x4(a[1], aAddr0 + 16 * G2_SA * 2 + ks * 32);
#pragma unroll
        for (int ni = 0; ni < 4; ni++) {
            uint32_t b[2];
            ldsm_x2t(b, bAddr0 + ks * 16 * G2_SB * 2 + ni * 16);
            mma_bf16(acc[0][ni], a[0], b);
            mma_bf16(acc[1][ni], a[1], b);
        }
    }

    // epilogue: out = x + acc + b2
    int row_in = lane >> 2, colq = (lane & 3) * 2;
#pragma unroll
    for (int mi = 0; mi < 2; mi++) {
#pragma unroll
        for (int h = 0; h < 2; h++) {
            int r = r0 + warp_m * 32 + mi * 16 + row_in + h * 8;
            if (r >= NB) continue;
            int b = r / NN, n = r - b * NN;
            size_t base = (size_t)(n * BB + b) * DD + c0 + warp_n * 32 + colq;
#pragma unroll
            for (int ni = 0; ni < 4; ni++) {
                size_t off = base + ni * 8;
                float2 bias = *(const float2*)(b2 + c0 + warp_n * 32 + ni * 8 + colq);
                float2 xv = *(const float2*)(x + off);
                float2 o = {xv.x + acc[mi][ni][2 * h]     + bias.x,
                            xv.y + acc[mi][ni][2 * h + 1] + bias.y};
                *(float2*)(out + off) = o;
            }
        }
    }
}

// ---------------------------------------------------------------------------
extern "C" void kernel_launch(void* const* d_in, const int* in_sizes, int n_in,
                              void* d_out, int out_size) {
    const float* x      = (const float*)d_in[0];
    const float* ln_w   = (const float*)d_in[1];
    const float* ln_b   = (const float*)d_in[2];
    const float* gamma  = (const float*)d_in[3];
    const float* gammax = (const float*)d_in[4];
    const float* w1     = (const float*)d_in[5];
    const float* b1     = (const float*)d_in[6];
    const float* w2     = (const float*)d_in[7];
    const float* b2     = (const float*)d_in[8];
    const float* dw3_w  = (const float*)d_in[9];
    const float* dw3_b  = (const float*)d_in[10];
    const float* dw5_w  = (const float*)d_in[11];
    const float* dw5_b  = (const float*)d_in[12];
    const float* dw7_w  = (const float*)d_in[13];
    const float* dw7_b  = (const float*)d_in[14];
    const float* proj_w = (const float*)d_in[15];
    const float* proj_b = (const float*)d_in[16];
    float* out = (float*)d_out;

    cudaFuncSetAttribute(k_conv, cudaFuncAttributeMaxDynamicSharedMemorySize,
                         (int)CONV_SMEM);

    k_prep<<<16, 256>>>(ln_w, ln_b, gamma, gammax, w1);
    k_fused1<<<(NB + 127) / 128, 256>>>(x, b1);
    k_conv<<<BB * 8, 256, CONV_SMEM>>>(dw3_w, dw3_b, dw5_w, dw5_b,
                                       dw7_w, dw7_b, proj_w, proj_b);
    k_gemm2<<<dim3((NB + 127) / 128, DD / 64), 256>>>(w2, b2, x, out);
}

// round 6
// speedup vs baseline: 2.3485x; 1.3450x over previous
#include <cuda_runtime.h>
#include <cuda_bf16.h>
#include <cstdint>
#include <stdint.h>
#include <math.h>

// Problem constants
#define BB   64
#define NN   1025
#define DD   1024
#define CC   64
#define NB   (BB*NN)          // 65600 rows
#define LN_EPS 1e-5f

// Scratch (device globals: allocation-free)
__device__ float g_y[(size_t)NB*CC];            // after GEMM1 (fp32, conv input)
__device__ __nv_bfloat16 g_z[(size_t)NB*CC];    // after conv+gelu (bf16, GEMM2 A)
__device__ __nv_bfloat16 g_w1a[(size_t)DD*CC];  // (ln_w*gamma) ⊙ w1, bf16
__device__ __nv_bfloat16 g_w1b[(size_t)DD*CC];  // gammax ⊙ w1, bf16
__device__ float g_S1p[16][CC];                 // partial col-sums of sc1*w1
__device__ float g_C3p[16][CC];                 // partial col-sums of sc3*w1

__device__ __forceinline__ float gelu_exact(float v) {
    return v * normcdff(v);
}
__device__ __forceinline__ unsigned smem_u32(const void* p) {
    return (unsigned)__cvta_generic_to_shared(p);
}
__device__ __forceinline__ void ldsm_x4(uint32_t (&r)[4], unsigned addr) {
    asm volatile("ldmatrix.sync.aligned.m8n8.x4.shared.b16 {%0,%1,%2,%3}, [%4];"
        : "=r"(r[0]), "=r"(r[1]), "=r"(r[2]), "=r"(r[3]) : "r"(addr));
}
__device__ __forceinline__ void ldsm_x2t(uint32_t (&r)[2], unsigned addr) {
    asm volatile("ldmatrix.sync.aligned.m8n8.x2.trans.shared.b16 {%0,%1}, [%2];"
        : "=r"(r[0]), "=r"(r[1]) : "r"(addr));
}
__device__ __forceinline__ void mma_bf16(float (&d)[4], const uint32_t (&a)[4],
                                         const uint32_t (&b)[2]) {
    asm volatile("mma.sync.aligned.m16n8k16.row.col.f32.bf16.bf16.f32 "
        "{%0,%1,%2,%3}, {%4,%5,%6,%7}, {%8,%9}, {%0,%1,%2,%3};"
        : "+f"(d[0]), "+f"(d[1]), "+f"(d[2]), "+f"(d[3])
        : "r"(a[0]), "r"(a[1]), "r"(a[2]), "r"(a[3]), "r"(b[0]), "r"(b[1]));
}
__device__ __forceinline__ void cp_async16(unsigned saddr, const void* gptr) {
    asm volatile("cp.async.cg.shared.global [%0], [%1], 16;" :: "r"(saddr), "l"(gptr));
}
__device__ __forceinline__ void cp_commit() {
    asm volatile("cp.async.commit_group;");
}
__device__ __forceinline__ void cp_wait0() {
    asm volatile("cp.async.wait_group 0;");
}

// ---------------------------------------------------------------------------
// Kernel 0: prep. Bake LN scales into w1 (bf16) + partial column sums.
// ---------------------------------------------------------------------------
__global__ __launch_bounds__(256) void k_prep(
    const float* __restrict__ ln_w, const float* __restrict__ ln_b,
    const float* __restrict__ gamma, const float* __restrict__ gammax,
    const float* __restrict__ w1)
{
    __shared__ float redS[4][CC];
    __shared__ float redC[4][CC];
    int tid = threadIdx.x;
    int k0 = blockIdx.x * 64;
    int c = tid & 63;
    int kg = tid >> 6;
    float s1p = 0.f, c3p = 0.f;
#pragma unroll
    for (int i = 0; i < 16; i++) {
        int kk = kg + 4 * i;
        int k = k0 + kk;
        float w = w1[(size_t)k * CC + c];
        float g = gamma[k];
        float sc1 = ln_w[k] * g;
        float sc3 = ln_b[k] * g;
        float sc2 = gammax[k];
        g_w1a[(size_t)k * CC + c] = __float2bfloat16(sc1 * w);
        g_w1b[(size_t)k * CC + c] = __float2bfloat16(sc2 * w);
        s1p += sc1 * w;
        c3p += sc3 * w;
    }
    redS[kg][c] = s1p;
    redC[kg][c] = c3p;
    __syncthreads();
    if (tid < 64) {
        g_S1p[blockIdx.x][tid] = redS[0][tid] + redS[1][tid] + redS[2][tid] + redS[3][tid];
        g_C3p[blockIdx.x][tid] = redC[0][tid] + redC[1][tid] + redC[2][tid] + redC[3][tid];
    }
}

// ---------------------------------------------------------------------------
// Kernel 1: fused LN-stats + decomposed GEMM1 with cp.async 2-stage pipeline.
// y = rs*acc1 + acc2 + C3 - mu*rs*S1 + b1.
// Tile 128 x 64, K-chunks of 64. 8 warps (4x2), warp tile 32x32.
// Dynamic smem: stage fp32 double-buffer + bf16 tiles.
// ---------------------------------------------------------------------------
#define F1_SA 72
#define F1_SB 72
#define F1_ST 68
#define F1_STAGE_SZ (128 * F1_ST)                      // floats, per buffer
#define F1_SMEM (2*F1_STAGE_SZ*4 + 128*F1_SA*2 + 64*F1_SB*2*2 + 2*CC*4 + 2*128*4 + 128*4)

__global__ __launch_bounds__(256, 2) void k_fused1(
    const float* __restrict__ x, const float* __restrict__ b1)
{
    extern __shared__ char fsm[];
    float* stage = (float*)fsm;                                    // 2 x 128*68 fp32
    __nv_bfloat16* sA  = (__nv_bfloat16*)(fsm + 2*F1_STAGE_SZ*4);  // 128*72 bf16
    __nv_bfloat16* sB1 = sA + 128 * F1_SA;                         // 64*72
    __nv_bfloat16* sB2 = sB1 + 64 * F1_SB;                         // 64*72
    float* sS1 = (float*)(sB2 + 64 * F1_SB);
    float* sC3 = sS1 + CC;
    float* smu = sC3 + CC;
    float* srs = smu + 128;
    int*   soff = (int*)(srs + 128);

    int tid = threadIdx.x;
    int lane = tid & 31, wid = tid >> 5;
    int warp_m = wid >> 1, warp_n = wid & 1;
    int r0 = blockIdx.x * 128;

    if (tid < 64) {
        float s1 = 0.f, c3 = 0.f;
#pragma unroll
        for (int p = 0; p < 16; p++) { s1 += g_S1p[p][tid]; c3 += g_C3p[p][tid]; }
        sS1[tid] = s1;
        sC3[tid] = c3;
    }
    if (tid < 128) {
        int r = r0 + tid;
        int rr = (r < NB) ? r : 0;
        int b = rr / NN;
        int n = rr - b * NN;
        soff[tid] = (n * BB + b) * DD;
    }
    __syncthreads();

    int rowA = tid >> 4;              // 0..15 (x8 strided)
    int kqA = (tid & 15) * 4;

    // prologue: issue A chunk 0
#pragma unroll
    for (int i = 0; i < 8; i++) {
        int row = rowA + 16 * i;
        cp_async16(smem_u32(&stage[row * F1_ST + kqA]),
                   x + soff[row] + kqA);
    }
    cp_commit();

    float acc1[2][4][4] = {};
    float acc2[2][4][4] = {};
    float sumx[8] = {}, sumxx[8] = {};

    unsigned aAddr0 = smem_u32(&sA[(warp_m * 32 + (lane & 15)) * F1_SA + (lane >> 4) * 8]);
    unsigned b1Addr0 = smem_u32(&sB1[(lane & 15) * F1_SB + warp_n * 32]);
    unsigned b2Addr0 = smem_u32(&sB2[(lane & 15) * F1_SB + warp_n * 32]);

    int pc = 0;
    for (int kc = 0; kc < DD; kc += 64, pc ^= 1) {
        cp_wait0();
        __syncthreads();   // stage[pc] visible to all; sA/sB free (prev MMA done)

        // issue next A chunk into the other buffer
        if (kc + 64 < DD) {
#pragma unroll
            for (int i = 0; i < 8; i++) {
                int row = rowA + 16 * i;
                cp_async16(smem_u32(&stage[(pc ^ 1) * F1_STAGE_SZ + row * F1_ST + kqA]),
                           x + soff[row] + kc + 64 + kqA);
            }
            cp_commit();
        }

        // B tiles: issue LDG early (L2 hits), consume after convert
        uint4 br1[2], br2[2];
#pragma unroll
        for (int i = 0; i < 2; i++) {
            int s = tid + i * 256;
            int kk = s >> 3;
            int q = (s & 7) * 8;
            br1[i] = *(const uint4*)(g_w1a + (size_t)(kc + kk) * CC + q);
            br2[i] = *(const uint4*)(g_w1b + (size_t)(kc + kk) * CC + q);
        }

        // convert staged fp32 -> bf16 sA, accumulating LN stats
#pragma unroll
        for (int i = 0; i < 8; i++) {
            int row = rowA + 16 * i;
            float4 v = *(const float4*)&stage[pc * F1_STAGE_SZ + row * F1_ST + kqA];
            sumx[i]  += v.x + v.y + v.z + v.w;
            sumxx[i] += v.x * v.x + v.y * v.y + v.z * v.z + v.w * v.w;
            *(__nv_bfloat162*)&sA[row * F1_SA + kqA]     = __floats2bfloat162_rn(v.x, v.y);
            *(__nv_bfloat162*)&sA[row * F1_SA + kqA + 2] = __floats2bfloat162_rn(v.z, v.w);
        }
        // store B
#pragma unroll
        for (int i = 0; i < 2; i++) {
            int s = tid + i * 256;
            int kk = s >> 3;
            int q = (s & 7) * 8;
            *(uint4*)&sB1[kk * F1_SB + q] = br1[i];
            *(uint4*)&sB2[kk * F1_SB + q] = br2[i];
        }
        __syncthreads();

#pragma unroll
        for (int ks = 0; ks < 4; ks++) {
            uint32_t a[2][4];
            ldsm_x4(a[0], aAddr0 + ks * 32);
            ldsm_x4(a[1], aAddr0 + 16 * F1_SA * 2 + ks * 32);
#pragma unroll
            for (int ni = 0; ni < 4; ni++) {
                uint32_t bb1[2], bb2[2];
                ldsm_x2t(bb1, b1Addr0 + ks * 16 * F1_SB * 2 + ni * 16);
                ldsm_x2t(bb2, b2Addr0 + ks * 16 * F1_SB * 2 + ni * 16);
#pragma unroll
                for (int mi = 0; mi < 2; mi++) {
                    mma_bf16(acc1[mi][ni], a[mi], bb1);
                    mma_bf16(acc2[mi][ni], a[mi], bb2);
                }
            }
        }
    }
    __syncthreads();

    // finalize row stats: reduce over the 16 lanes sharing each row
#pragma unroll
    for (int i = 0; i < 8; i++) {
#pragma unroll
        for (int o = 8; o; o >>= 1) {
            sumx[i]  += __shfl_xor_sync(0xffffffffu, sumx[i], o);
            sumxx[i] += __shfl_xor_sync(0xffffffffu, sumxx[i], o);
        }
    }
    if ((tid & 15) == 0) {
#pragma unroll
        for (int i = 0; i < 8; i++) {
            int row = rowA + 16 * i;
            float m = sumx[i] * (1.f / DD);
            float var = sumxx[i] * (1.f / DD) - m * m;
            smu[row] = m;
            srs[row] = rsqrtf(var + LN_EPS);
        }
    }
    __syncthreads();

    // epilogue
    int row_in = lane >> 2;
    int colq = (lane & 3) * 2;
#pragma unroll
    for (int mi = 0; mi < 2; mi++) {
#pragma unroll
        for (int h = 0; h < 2; h++) {
            int rl = warp_m * 32 + mi * 16 + row_in + h * 8;
            int r = r0 + rl;
            if (r >= NB) continue;
            float mu = smu[rl], rs = srs[rl];
            float mrs = mu * rs;
#pragma unroll
            for (int ni = 0; ni < 4; ni++) {
                int col = warp_n * 32 + ni * 8 + colq;
                float2 bias = *(const float2*)(b1 + col);
                float v0 = rs * acc1[mi][ni][2 * h]     + acc2[mi][ni][2 * h]
                         + sC3[col]     - mrs * sS1[col]     + bias.x;
                float v1 = rs * acc1[mi][ni][2 * h + 1] + acc2[mi][ni][2 * h + 1]
                         + sC3[col + 1] - mrs * sS1[col + 1] + bias.y;
                *(float2*)(g_y + (size_t)r * CC + col) = make_float2(v0, v1);
            }
        }
    }
}

// ---------------------------------------------------------------------------
// Kernel 3: multi-scale depthwise conv (collapsed 7x7) + residual + 1x1 proj
//           + residual + exact GELU -> z (bf16). 2-row strips, 2 blocks/SM.
// ---------------------------------------------------------------------------
#define CV_ROWS 8            // 2 output rows + 6 halo
#define CV_COLS 38
#define CV_STRIDE (CV_COLS * 64)
#define CV_SIN (CV_ROWS * CV_STRIDE)      // 19456 floats
#define CV_S2  (2 * 32 * 64)              // 4096
#define CV_PW  (64 * 64)                  // 4096
#define CONV_SMEM ((CV_SIN + CV_S2 + CV_PW) * sizeof(float))   // 110592 B

__global__ __launch_bounds__(256, 2) void k_conv(
    const float* __restrict__ dw3_w, const float* __restrict__ dw3_b,
    const float* __restrict__ dw5_w, const float* __restrict__ dw5_b,
    const float* __restrict__ dw7_w, const float* __restrict__ dw7_b,
    const float* __restrict__ proj_w, const float* __restrict__ proj_b)
{
    extern __shared__ float sm[];
    float* sIn = sm;
    float* s2  = sm + CV_SIN;
    float* pws = s2 + CV_S2;

    int tid = threadIdx.x;
    int b = blockIdx.x >> 4;
    int strip = blockIdx.x & 15;
    int i0 = strip * 2;
    const float* yb = g_y + (size_t)b * NN * CC;

    for (int idx = tid; idx < CV_SIN; idx += 256) {
        int rr  = idx / CV_STRIDE;
        int rem = idx - rr * CV_STRIDE;
        int col = rem >> 6;
        int c   = rem & 63;
        int gy = i0 - 3 + rr;
        int gx = col - 3;
        float v = 0.f;
        if (gy >= 0 && gy < 32 && gx >= 0 && gx < 32)
            v = yb[(size_t)(1 + gy * 32 + gx) * CC + c];
        sIn[idx] = v;
    }
    for (int idx = tid; idx < CV_PW; idx += 256) {
        int c = idx >> 6, o = idx & 63;
        pws[idx] = proj_w[(size_t)o * CC + c];
    }

    int c = tid & 63;
    float wreg[49];
    float beff;
    {
        const float* w7 = dw7_w + c * 49;
        const float* w5 = dw5_w + c * 25;
        const float* w3 = dw3_w + c * 9;
#pragma unroll
        for (int dy = 0; dy < 7; dy++)
#pragma unroll
            for (int dx = 0; dx < 7; dx++) {
                float v = w7[dy * 7 + dx];
                if (dy >= 1 && dy <= 5 && dx >= 1 && dx <= 5) v += w5[(dy - 1) * 5 + (dx - 1)];
                if (dy >= 2 && dy <= 4 && dx >= 2 && dx <= 4) v += w3[(dy - 2) * 3 + (dx - 2)];
                wreg[dy * 7 + dx] = v * (1.f / 3.f);
            }
        beff = (dw3_b[c] + dw5_b[c] + dw7_b[c]) * (1.f / 3.f);
    }
    __syncthreads();

    // conv phase: thread = (col-half, row in {0,1}, channel), sweeps 16 cols
    int row = (tid >> 6) & 1;
    int jbase = (tid >> 7) * 16;
#pragma unroll 2
    for (int jj = 0; jj < 16; jj++) {
        int j = jbase + jj;
        float acc = beff;
#pragma unroll
        for (int dy = 0; dy < 7; dy++) {
            const float* rp = sIn + ((row + dy) * CV_COLS + j) * 64 + c;
#pragma unroll
            for (int dx = 0; dx < 7; dx++)
                acc += rp[dx * 64] * wreg[dy * 7 + dx];
        }
        float center = sIn[((row + 3) * CV_COLS + (j + 3)) * 64 + c];
        s2[(row * 32 + j) * 64 + c] = acc + center;
    }
    __syncthreads();

    // proj phase: 64 px, thread = (px group of 4, out-col group of 4)
    int og = tid & 15, pg = tid >> 4;
    int o0 = og * 4, px0 = pg * 4;
    float pacc[4][4] = {};
    for (int cc = 0; cc < 64; cc++) {
        float wv[4];
        *(float4*)wv = *(const float4*)&pws[cc * 64 + o0];
#pragma unroll
        for (int i = 0; i < 4; i++) {
            float sv = s2[(px0 + i) * 64 + cc];
#pragma unroll
            for (int j = 0; j < 4; j++) pacc[i][j] += sv * wv[j];
        }
    }
    float pb[4];
    *(float4*)pb = *(const float4*)(proj_b + o0);
#pragma unroll
    for (int i = 0; i < 4; i++) {
        int px = px0 + i;
        size_t zoff = ((size_t)b * NN + 1 + i0 * 32 + px) * CC + o0;
        float v0 = gelu_exact(s2[px * 64 + o0 + 0] + pacc[i][0] + pb[0]);
        float v1 = gelu_exact(s2[px * 64 + o0 + 1] + pacc[i][1] + pb[1]);
        float v2 = gelu_exact(s2[px * 64 + o0 + 2] + pacc[i][2] + pb[2]);
        float v3 = gelu_exact(s2[px * 64 + o0 + 3] + pacc[i][3] + pb[3]);
        *(__nv_bfloat162*)(g_z + zoff)     = __floats2bfloat162_rn(v0, v1);
        *(__nv_bfloat162*)(g_z + zoff + 2) = __floats2bfloat162_rn(v2, v3);
    }

    if (strip == 0 && tid < 64) {
        float v = yb[tid];
        g_z[(size_t)b * NN * CC + tid] = __float2bfloat16(gelu_exact(v));
    }
}

// ---------------------------------------------------------------------------
// Kernel 4: z(bf16) @ w2 + b2 + identity(x) -> out. Tile 128x64, K=64.
// ---------------------------------------------------------------------------
#define G2_SA 72
#define G2_SB 72

__global__ __launch_bounds__(256) void k_gemm2(
    const float* __restrict__ w2, const float* __restrict__ b2,
    const float* __restrict__ x, float* __restrict__ out)
{
    __shared__ __nv_bfloat16 sA[128 * G2_SA];  // 18432 B
    __shared__ __nv_bfloat16 sB[64 * G2_SB];   //  9216 B

    int tid = threadIdx.x, lane = tid & 31, wid = tid >> 5;
    int warp_m = wid >> 1, warp_n = wid & 1;
    int r0 = blockIdx.x * 128;
    int c0 = blockIdx.y * 64;

    // A tile: z bf16, 128 x 64
#pragma unroll
    for (int i = 0; i < 4; i++) {
        int s = tid + i * 256;
        int row = s >> 3;
        int cq = (s & 7) * 8;
        int r = r0 + row;
        uint4 v = make_uint4(0, 0, 0, 0);
        if (r < NB) v = *(const uint4*)(g_z + (size_t)r * CC + cq);
        *(uint4*)&sA[row * G2_SA + cq] = v;
    }
    // B tile: w2[0..63][c0..c0+63] fp32 -> bf16
#pragma unroll
    for (int i = 0; i < 4; i++) {
        int s = tid + i * 256;
        int k = s >> 4;
        int cc = (s & 15) * 4;
        float4 v = *(const float4*)(w2 + (size_t)k * DD + c0 + cc);
        *(__nv_bfloat162*)&sB[k * G2_SB + cc]     = __floats2bfloat162_rn(v.x, v.y);
        *(__nv_bfloat162*)&sB[k * G2_SB + cc + 2] = __floats2bfloat162_rn(v.z, v.w);
    }
    __syncthreads();

    float acc[2][4][4] = {};
    unsigned aAddr0 = smem_u32(&sA[(warp_m * 32 + (lane & 15)) * G2_SA + (lane >> 4) * 8]);
    unsigned bAddr0 = smem_u32(&sB[(lane & 15) * G2_SB + warp_n * 32]);

#pragma unroll
    for (int ks = 0; ks < 4; ks++) {
        uint32_t a[2][4];
        ldsm_x4(a[0], aAddr0 + ks * 32);
        ldsm_x4(a[1], aAddr0 + 16 * G2_SA * 2 + ks * 32);
#pragma unroll
        for (int ni = 0; ni < 4; ni++) {
            uint32_t b[2];
            ldsm_x2t(b, bAddr0 + ks * 16 * G2_SB * 2 + ni * 16);
            mma_bf16(acc[0][ni], a[0], b);
            mma_bf16(acc[1][ni], a[1], b);
        }
    }

    // epilogue: out = x + acc + b2
    int row_in = lane >> 2, colq = (lane & 3) * 2;
#pragma unroll
    for (int mi = 0; mi < 2; mi++) {
#pragma unroll
        for (int h = 0; h < 2; h++) {
            int r = r0 + warp_m * 32 + mi * 16 + row_in + h * 8;
            if (r >= NB) continue;
            int b = r / NN, n = r - b * NN;
            size_t base = (size_t)(n * BB + b) * DD + c0 + warp_n * 32 + colq;
#pragma unroll
            for (int ni = 0; ni < 4; ni++) {
                size_t off = base + ni * 8;
                float2 bias = *(const float2*)(b2 + c0 + warp_n * 32 + ni * 8 + colq);
                float2 xv = *(const float2*)(x + off);
                float2 o = {xv.x + acc[mi][ni][2 * h]     + bias.x,
                            xv.y + acc[mi][ni][2 * h + 1] + bias.y};
                *(float2*)(out + off) = o;
            }
        }
    }
}

// ---------------------------------------------------------------------------
extern "C" void kernel_launch(void* const* d_in, const int* in_sizes, int n_in,
                              void* d_out, int out_size) {
    const float* x      = (const float*)d_in[0];
    const float* ln_w   = (const float*)d_in[1];
    const float* ln_b   = (const float*)d_in[2];
    const float* gamma  = (const float*)d_in[3];
    const float* gammax = (const float*)d_in[4];
    const float* w1     = (const float*)d_in[5];
    const float* b1     = (const float*)d_in[6];
    const float* w2     = (const float*)d_in[7];
    const float* b2     = (const float*)d_in[8];
    const float* dw3_w  = (const float*)d_in[9];
    const float* dw3_b  = (const float*)d_in[10];
    const float* dw5_w  = (const float*)d_in[11];
    const float* dw5_b  = (const float*)d_in[12];
    const float* dw7_w  = (const float*)d_in[13];
    const float* dw7_b  = (const float*)d_in[14];
    const float* proj_w = (const float*)d_in[15];
    const float* proj_b = (const float*)d_in[16];
    float* out = (float*)d_out;

    cudaFuncSetAttribute(k_fused1, cudaFuncAttributeMaxDynamicSharedMemorySize,
                         (int)F1_SMEM);
    cudaFuncSetAttribute(k_conv, cudaFuncAttributeMaxDynamicSharedMemorySize,
                         (int)CONV_SMEM);

    k_prep<<<16, 256>>>(ln_w, ln_b, gamma, gammax, w1);
    k_fused1<<<(NB + 127) / 128, 256, F1_SMEM>>>(x, b1);
    k_conv<<<BB * 16, 256, CONV_SMEM>>>(dw3_w, dw3_b, dw5_w, dw5_b,
                                        dw7_w, dw7_b, proj_w, proj_b);
    k_gemm2<<<dim3((NB + 127) / 128, DD / 64), 256>>>(w2, b2, x, out);
}